// round 1
// baseline (speedup 1.0000x reference)
#include <cuda_runtime.h>
#include <cstddef>

#define NN   50000      // nodes of g
#define NE   400000     // edges of g == nodes of lg
#define NLE  3200000    // edges of lg
#define F    32

// ---------------- scratch (device globals: no allocation allowed) ----------------
__device__ float d_zg0[NN * F];
__device__ float d_zg1[NN * F];
__device__ float d_zg2[NN * F];
__device__ float d_zgt[NN * F];
__device__ float d_pmy[NN * F];
__device__ float d_zl0[NE * F];
__device__ float d_zl1[NE * F];
__device__ float d_zl2[NE * F];
__device__ float d_zlt[NE * F];
__device__ float d_stats[128];   // [0:32) sum_x, [32:64) sumsq_x, [64:96) sum_y, [96:128) sumsq_y

// ---------------- SpMM: out[dst[e]] += z[src[e]], 8 threads per edge ----------------
__global__ void spmm_kernel(const float* __restrict__ z, const int* __restrict__ src,
                            const int* __restrict__ dst, float* __restrict__ out, int nE) {
    long long t = (long long)blockIdx.x * blockDim.x + threadIdx.x;
    int e = (int)(t >> 3);
    if (e >= nE) return;
    int lane = (int)(t & 7);
    int s = __ldg(src + e);
    int d = __ldg(dst + e);
    float4 v = *((const float4*)(z + (size_t)s * F) + lane);
    float* op = out + (size_t)d * F + lane * 4;
    asm volatile("red.global.add.v4.f32 [%0], {%1, %2, %3, %4};"
                 :: "l"(op), "f"(v.x), "f"(v.y), "f"(v.z), "f"(v.w) : "memory");
}

// ---------------- copy_edge + sum: out[dst[e]] += y[e] ----------------
__global__ void segsum_kernel(const float* __restrict__ y, const int* __restrict__ dst,
                              float* __restrict__ out, int nE) {
    long long t = (long long)blockIdx.x * blockDim.x + threadIdx.x;
    int e = (int)(t >> 3);
    if (e >= nE) return;
    int lane = (int)(t & 7);
    int d = __ldg(dst + e);
    float4 v = *((const float4*)(y + (size_t)e * F) + lane);
    float* op = out + (size_t)d * F + lane * 4;
    asm volatile("red.global.add.v4.f32 [%0], {%1, %2, %3, %4};"
                 :: "l"(op), "f"(v.x), "f"(v.y), "f"(v.z), "f"(v.w) : "memory");
}

// ---------------- fused 6-matvec assemble + half_relu ----------------
// out[r] = W0*base + W1*(deg*base) + W2*extra + L0*z0 + L1*z1 + L2*z2 + Σb, then relu cols 16..31
__device__ __forceinline__ void mv_acc(float acc[F], const float* __restrict__ vec,
                                       float scale, const float (&W)[F][F]) {
    const float4* vp = (const float4*)vec;
#pragma unroll
    for (int k4 = 0; k4 < 8; k4++) {
        float4 v = vp[k4];
        float a0 = v.x * scale, a1 = v.y * scale, a2 = v.z * scale, a3 = v.w * scale;
#pragma unroll
        for (int j = 0; j < F; j++) {
            acc[j] = fmaf(a0, W[k4 * 4 + 0][j], acc[j]);
            acc[j] = fmaf(a1, W[k4 * 4 + 1][j], acc[j]);
            acc[j] = fmaf(a2, W[k4 * 4 + 2][j], acc[j]);
            acc[j] = fmaf(a3, W[k4 * 4 + 3][j], acc[j]);
        }
    }
}

__global__ void assemble_kernel(
    const float* __restrict__ base, const float* __restrict__ deg,
    const float* __restrict__ extra, const int* __restrict__ gatherIdx,
    const float* __restrict__ z0, const float* __restrict__ z1, const float* __restrict__ z2,
    const float* __restrict__ Wmain, const float* __restrict__ bmain,
    const float* __restrict__ Wlist, const float* __restrict__ blist,
    float* __restrict__ out, int n)
{
    __shared__ float Ws[6][F][F];  // [matrix][k][j]  (transposed for broadcast reads)
    __shared__ float bs[F];
    for (int i = threadIdx.x; i < 6 * F * F; i += blockDim.x) {
        int m = i >> 10, j = (i >> 5) & 31, k = i & 31;
        float w = (m < 3) ? Wmain[m * 1024 + j * 32 + k] : Wlist[(m - 3) * 1024 + j * 32 + k];
        Ws[m][k][j] = w;
    }
    if (threadIdx.x < F) {
        float b = 0.f;
#pragma unroll
        for (int m = 0; m < 3; m++) b += bmain[m * 32 + threadIdx.x] + blist[m * 32 + threadIdx.x];
        bs[threadIdx.x] = b;
    }
    __syncthreads();

    int r = blockIdx.x * blockDim.x + threadIdx.x;
    if (r >= n) return;

    float acc[F];
#pragma unroll
    for (int j = 0; j < F; j++) acc[j] = bs[j];

    size_t r32 = (size_t)r * F;
    float dg = deg[r];
    mv_acc(acc, base + r32, 1.f, Ws[0]);
    mv_acc(acc, base + r32, dg,  Ws[1]);
    const float* ex = gatherIdx ? (extra + (size_t)__ldg(gatherIdx + r) * F) : (extra + r32);
    mv_acc(acc, ex,        1.f, Ws[2]);
    mv_acc(acc, z0 + r32,  1.f, Ws[3]);
    mv_acc(acc, z1 + r32,  1.f, Ws[4]);
    mv_acc(acc, z2 + r32,  1.f, Ws[5]);

#pragma unroll
    for (int j = F / 2; j < F; j++) acc[j] = fmaxf(acc[j], 0.f);

    float4* op = (float4*)(out + r32);
#pragma unroll
    for (int j = 0; j < 8; j++)
        op[j] = make_float4(acc[4 * j], acc[4 * j + 1], acc[4 * j + 2], acc[4 * j + 3]);
}

// ---------------- BN stats: per-column sum / sumsq ----------------
__global__ void stats_kernel(const float* __restrict__ v, long long nRows, float* __restrict__ st) {
    int col = threadIdx.x & 31;
    int w = threadIdx.x >> 5;
    int warpsPerBlock = blockDim.x >> 5;
    float s = 0.f, s2 = 0.f;
    for (long long r = (long long)blockIdx.x * warpsPerBlock + w; r < nRows;
         r += (long long)gridDim.x * warpsPerBlock) {
        float val = v[r * F + col];
        s += val;
        s2 += val * val;
    }
    __shared__ float sm[2][8][F];
    sm[0][w][col] = s;
    sm[1][w][col] = s2;
    __syncthreads();
    if (threadIdx.x < F) {
        float a = 0.f, b = 0.f;
#pragma unroll
        for (int ww = 0; ww < 8; ww++) { a += sm[0][ww][threadIdx.x]; b += sm[1][ww][threadIdx.x]; }
        atomicAdd(&st[threadIdx.x], a);
        atomicAdd(&st[F + threadIdx.x], b);
    }
}

// ---------------- BN normalize (in-place on output) ----------------
__global__ void normalize_kernel(float* __restrict__ v, long long nRows,
                                 const float* __restrict__ st,
                                 const float* __restrict__ scale, const float* __restrict__ bias) {
    __shared__ float mulc[F], addc[F];
    if (threadIdx.x < F) {
        float m = st[threadIdx.x] / (float)nRows;
        float var = st[F + threadIdx.x] / (float)nRows - m * m;
        float inv = rsqrtf(var + 1e-5f);
        float g = inv * scale[threadIdx.x];
        mulc[threadIdx.x] = g;
        addc[threadIdx.x] = bias[threadIdx.x] - m * g;
    }
    __syncthreads();
    int col = threadIdx.x & 31;
    int w = threadIdx.x >> 5;
    int warpsPerBlock = blockDim.x >> 5;
    for (long long r = (long long)blockIdx.x * warpsPerBlock + w; r < nRows;
         r += (long long)gridDim.x * warpsPerBlock) {
        v[r * F + col] = fmaf(v[r * F + col], mulc[col], addc[col]);
    }
}

// ---------------- launcher ----------------
extern "C" void kernel_launch(void* const* d_in, const int* in_sizes, int n_in,
                              void* d_out, int out_size) {
    const float* x            = (const float*)d_in[0];
    const float* y            = (const float*)d_in[1];
    const float* deg_g        = (const float*)d_in[2];
    const float* deg_lg       = (const float*)d_in[3];
    const float* theta_main_w = (const float*)d_in[4];
    const float* theta_main_b = (const float*)d_in[5];
    const float* theta_list_w = (const float*)d_in[6];
    const float* theta_list_b = (const float*)d_in[7];
    const float* gamma_main_w = (const float*)d_in[8];
    const float* gamma_main_b = (const float*)d_in[9];
    const float* gamma_list_w = (const float*)d_in[10];
    const float* gamma_list_b = (const float*)d_in[11];
    const float* bn_x_scale   = (const float*)d_in[12];
    const float* bn_x_bias    = (const float*)d_in[13];
    const float* bn_y_scale   = (const float*)d_in[14];
    const float* bn_y_bias    = (const float*)d_in[15];
    const int*   g_src        = (const int*)d_in[16];
    const int*   g_dst        = (const int*)d_in[17];
    const int*   lg_src       = (const int*)d_in[18];
    const int*   lg_dst       = (const int*)d_in[19];
    const int*   pm_pd        = (const int*)d_in[20];

    float* out_x = (float*)d_out;
    float* out_y = (float*)d_out + (size_t)NN * F;

    float *zg0, *zg1, *zg2, *zgt, *pmy, *zl0, *zl1, *zl2, *zlt, *st;
    cudaGetSymbolAddress((void**)&zg0, d_zg0);
    cudaGetSymbolAddress((void**)&zg1, d_zg1);
    cudaGetSymbolAddress((void**)&zg2, d_zg2);
    cudaGetSymbolAddress((void**)&zgt, d_zgt);
    cudaGetSymbolAddress((void**)&pmy, d_pmy);
    cudaGetSymbolAddress((void**)&zl0, d_zl0);
    cudaGetSymbolAddress((void**)&zl1, d_zl1);
    cudaGetSymbolAddress((void**)&zl2, d_zl2);
    cudaGetSymbolAddress((void**)&zlt, d_zlt);
    cudaGetSymbolAddress((void**)&st,  d_stats);

    const int TB = 256;
    int blocksG  = (NE * 8 + TB - 1) / TB;    // 12500
    int blocksLG = (int)(((long long)NLE * 8 + TB - 1) / TB);  // 100000
    size_t szN = (size_t)NN * F * sizeof(float);
    size_t szE = (size_t)NE * F * sizeof(float);

    // ----- x branch: aggregate over g (hops 1, 2, 4) -----
    cudaMemsetAsync(zg0, 0, szN);
    spmm_kernel<<<blocksG, TB>>>(x, g_src, g_dst, zg0, NE);
    cudaMemsetAsync(zg1, 0, szN);
    spmm_kernel<<<blocksG, TB>>>(zg0, g_src, g_dst, zg1, NE);
    cudaMemsetAsync(zgt, 0, szN);
    spmm_kernel<<<blocksG, TB>>>(zg1, g_src, g_dst, zgt, NE);
    cudaMemsetAsync(zg2, 0, szN);
    spmm_kernel<<<blocksG, TB>>>(zgt, g_src, g_dst, zg2, NE);
    // pmpd_y = segment_sum(y, g_dst)
    cudaMemsetAsync(pmy, 0, szN);
    segsum_kernel<<<blocksG, TB>>>(y, g_dst, pmy, NE);

    assemble_kernel<<<(NN + TB - 1) / TB, TB>>>(
        x, deg_g, pmy, nullptr, zg0, zg1, zg2,
        theta_main_w, theta_main_b, theta_list_w, theta_list_b, out_x, NN);

    // ----- y branch: aggregate over lg (hops 1, 2, 4) -----
    cudaMemsetAsync(zl0, 0, szE);
    spmm_kernel<<<blocksLG, TB>>>(y, lg_src, lg_dst, zl0, NLE);
    cudaMemsetAsync(zl1, 0, szE);
    spmm_kernel<<<blocksLG, TB>>>(zl0, lg_src, lg_dst, zl1, NLE);
    cudaMemsetAsync(zlt, 0, szE);
    spmm_kernel<<<blocksLG, TB>>>(zl1, lg_src, lg_dst, zlt, NLE);
    cudaMemsetAsync(zl2, 0, szE);
    spmm_kernel<<<blocksLG, TB>>>(zlt, lg_src, lg_dst, zl2, NLE);

    assemble_kernel<<<(NE + TB - 1) / TB, TB>>>(
        y, deg_lg, x, pm_pd, zl0, zl1, zl2,
        gamma_main_w, gamma_main_b, gamma_list_w, gamma_list_b, out_y, NE);

    // ----- batchnorm (training-mode, biased var) -----
    cudaMemsetAsync(st, 0, 128 * sizeof(float));
    stats_kernel<<<2048, TB>>>(out_x, NN, st);
    stats_kernel<<<2048, TB>>>(out_y, NE, st + 64);
    normalize_kernel<<<2048, TB>>>(out_x, NN, st, bn_x_scale, bn_x_bias);
    normalize_kernel<<<2048, TB>>>(out_y, NE, st + 64, bn_y_scale, bn_y_bias);
}

// round 2
// speedup vs baseline: 1.3390x; 1.3390x over previous
#include <cuda_runtime.h>
#include <cstddef>

#define NN   50000      // nodes of g
#define NE   400000     // edges of g == nodes of lg
#define NLE  3200000    // edges of lg
#define F    32
#define SCAN_B 1024

typedef unsigned long long u64;

// ---------------- scratch (device globals: no allocation allowed) ----------------
__device__ float d_zg0[NN * F];
__device__ float d_zg1[NN * F];
__device__ float d_zg2[NN * F];
__device__ float d_zgt[NN * F];
__device__ float d_pmy[NN * F];
__device__ float d_zl0[NE * F];
__device__ float d_zl1[NE * F];
__device__ float d_zl2[NE * F];
__device__ float d_zlt[NE * F];
__device__ float d_stats[128];

// CSR scratch
__device__ int d_cnt_g[NN];
__device__ int d_off_g[NN + 1];
__device__ int d_cur_g[NN];
__device__ int d_csr_src_g[NE];
__device__ int d_csr_eid_g[NE];
__device__ int d_cnt_lg[NE];
__device__ int d_off_lg[NE + 1];
__device__ int d_cur_lg[NE];
__device__ int d_csr_lg[NLE];
__device__ int d_bsum[1024];

// ---------------- f32x2 helpers ----------------
__device__ __forceinline__ u64 pack2(float a, float b) {
    u64 r; asm("mov.b64 %0, {%1, %2};" : "=l"(r) : "f"(a), "f"(b)); return r;
}
__device__ __forceinline__ void unpack2(u64 v, float& a, float& b) {
    asm("mov.b64 {%0, %1}, %2;" : "=f"(a), "=f"(b) : "l"(v));
}
__device__ __forceinline__ u64 fma2(u64 a, u64 b, u64 c) {
    u64 d; asm("fma.rn.f32x2 %0, %1, %2, %3;" : "=l"(d) : "l"(a), "l"(b), "l"(c)); return d;
}

// ---------------- CSR build ----------------
__global__ void hist_kernel(const int* __restrict__ dst, int nE, int* __restrict__ cnt) {
    int e = blockIdx.x * blockDim.x + threadIdx.x;
    if (e < nE) atomicAdd(&cnt[__ldg(dst + e)], 1);
}

__global__ void scan_block_kernel(const int* __restrict__ cnt, int n,
                                  int* __restrict__ incl, int* __restrict__ bsum) {
    __shared__ int sm[SCAN_B];
    int i = blockIdx.x * SCAN_B + threadIdx.x;
    int v = (i < n) ? cnt[i] : 0;
    sm[threadIdx.x] = v;
    __syncthreads();
    for (int o = 1; o < SCAN_B; o <<= 1) {
        int t = (threadIdx.x >= o) ? sm[threadIdx.x - o] : 0;
        __syncthreads();
        sm[threadIdx.x] += t;
        __syncthreads();
    }
    if (i < n) incl[i] = sm[threadIdx.x];
    if (threadIdx.x == SCAN_B - 1) bsum[blockIdx.x] = sm[threadIdx.x];
}

__global__ void scan_bsums_kernel(int* __restrict__ bsum, int nb) {
    __shared__ int sm[SCAN_B];
    int v = (threadIdx.x < nb) ? bsum[threadIdx.x] : 0;
    sm[threadIdx.x] = v;
    __syncthreads();
    for (int o = 1; o < SCAN_B; o <<= 1) {
        int t = (threadIdx.x >= o) ? sm[threadIdx.x - o] : 0;
        __syncthreads();
        sm[threadIdx.x] += t;
        __syncthreads();
    }
    if (threadIdx.x < nb) bsum[threadIdx.x] = sm[threadIdx.x] - v;  // exclusive
}

__global__ void scan_add_kernel(const int* __restrict__ incl, int n,
                                const int* __restrict__ bsum, int* __restrict__ off) {
    int i = blockIdx.x * SCAN_B + threadIdx.x;
    if (i < n) off[i + 1] = incl[i] + bsum[blockIdx.x];
    if (i == 0) off[0] = 0;
}

__global__ void fill_lg_kernel(const int* __restrict__ src, const int* __restrict__ dst,
                               int nE, int* __restrict__ cur, int* __restrict__ csr) {
    int e = blockIdx.x * blockDim.x + threadIdx.x;
    if (e >= nE) return;
    int p = atomicAdd(&cur[__ldg(dst + e)], 1);
    csr[p] = __ldg(src + e);
}

__global__ void fill_g_kernel(const int* __restrict__ src, const int* __restrict__ dst,
                              int nE, int* __restrict__ cur,
                              int* __restrict__ csr_s, int* __restrict__ csr_e) {
    int e = blockIdx.x * blockDim.x + threadIdx.x;
    if (e >= nE) return;
    int p = atomicAdd(&cur[__ldg(dst + e)], 1);
    csr_s[p] = __ldg(src + e);
    csr_e[p] = e;
}

// ---------------- pull SpMM: out[r] = sum over i in [off[r],off[r+1]) of z[idx[i]] ----------------
// 8 threads per row, each owns a float4 column slice.
__global__ void spmm_pull_kernel(const float* __restrict__ z, const int* __restrict__ off,
                                 const int* __restrict__ idx, float* __restrict__ out, int nRows) {
    long long t = (long long)blockIdx.x * blockDim.x + threadIdx.x;
    int r = (int)(t >> 3);
    if (r >= nRows) return;
    int lane = (int)(t & 7);
    int b = __ldg(off + r), e = __ldg(off + r + 1);
    float4 acc = make_float4(0.f, 0.f, 0.f, 0.f);
    int i = b;
    for (; i + 1 < e; i += 2) {
        int s0 = __ldg(idx + i);
        int s1 = __ldg(idx + i + 1);
        float4 v0 = *((const float4*)(z + (size_t)s0 * F) + lane);
        float4 v1 = *((const float4*)(z + (size_t)s1 * F) + lane);
        acc.x += v0.x + v1.x; acc.y += v0.y + v1.y;
        acc.z += v0.z + v1.z; acc.w += v0.w + v1.w;
    }
    if (i < e) {
        int s0 = __ldg(idx + i);
        float4 v0 = *((const float4*)(z + (size_t)s0 * F) + lane);
        acc.x += v0.x; acc.y += v0.y; acc.z += v0.z; acc.w += v0.w;
    }
    *((float4*)(out + (size_t)r * F) + lane) = acc;
}

// ---------------- fused 6-matvec assemble (f32x2) + half_relu ----------------
__device__ __forceinline__ void mv_acc2(u64 acc[16], const float* __restrict__ vec,
                                        float scale, const u64 (&W)[F][16]) {
    const float4* vp = (const float4*)vec;
#pragma unroll 1
    for (int k4 = 0; k4 < 8; k4++) {
        float4 v = vp[k4];
        float c0 = v.x * scale, c1 = v.y * scale, c2 = v.z * scale, c3 = v.w * scale;
        u64 a0 = pack2(c0, c0), a1 = pack2(c1, c1), a2 = pack2(c2, c2), a3 = pack2(c3, c3);
#pragma unroll
        for (int j = 0; j < 16; j++) acc[j] = fma2(a0, W[k4 * 4 + 0][j], acc[j]);
#pragma unroll
        for (int j = 0; j < 16; j++) acc[j] = fma2(a1, W[k4 * 4 + 1][j], acc[j]);
#pragma unroll
        for (int j = 0; j < 16; j++) acc[j] = fma2(a2, W[k4 * 4 + 2][j], acc[j]);
#pragma unroll
        for (int j = 0; j < 16; j++) acc[j] = fma2(a3, W[k4 * 4 + 3][j], acc[j]);
    }
}

__global__ void assemble_kernel(
    const float* __restrict__ base, const float* __restrict__ deg,
    const float* __restrict__ extra, const int* __restrict__ gatherIdx,
    const float* __restrict__ z0, const float* __restrict__ z1, const float* __restrict__ z2,
    const float* __restrict__ Wmain, const float* __restrict__ bmain,
    const float* __restrict__ Wlist, const float* __restrict__ blist,
    float* __restrict__ out, int n)
{
    __shared__ u64 sW[6][F][16];   // [matrix][k][jpair], pair = cols (2j, 2j+1)
    __shared__ u64 sb[16];
    for (int i = threadIdx.x; i < 6 * F * 16; i += blockDim.x) {
        int m = i >> 9;            // /512
        int rem = i & 511;
        int k = rem >> 4;
        int j2 = rem & 15;
        const float* W = (m < 3) ? (Wmain + m * 1024) : (Wlist + (m - 3) * 1024);
        float w0 = W[(2 * j2) * 32 + k];
        float w1 = W[(2 * j2 + 1) * 32 + k];
        sW[m][k][j2] = pack2(w0, w1);
    }
    if (threadIdx.x < 16) {
        int j2 = threadIdx.x;
        float b0 = 0.f, b1 = 0.f;
#pragma unroll
        for (int m = 0; m < 3; m++) {
            b0 += bmain[m * 32 + 2 * j2] + blist[m * 32 + 2 * j2];
            b1 += bmain[m * 32 + 2 * j2 + 1] + blist[m * 32 + 2 * j2 + 1];
        }
        sb[j2] = pack2(b0, b1);
    }
    __syncthreads();

    int r = blockIdx.x * blockDim.x + threadIdx.x;
    if (r >= n) return;

    u64 acc[16];
#pragma unroll
    for (int j = 0; j < 16; j++) acc[j] = sb[j];

    size_t r32 = (size_t)r * F;
    float dg = deg[r];
    mv_acc2(acc, base + r32, 1.f, sW[0]);
    mv_acc2(acc, base + r32, dg,  sW[1]);
    const float* ex = gatherIdx ? (extra + (size_t)__ldg(gatherIdx + r) * F) : (extra + r32);
    mv_acc2(acc, ex,        1.f, sW[2]);
    mv_acc2(acc, z0 + r32,  1.f, sW[3]);
    mv_acc2(acc, z1 + r32,  1.f, sW[4]);
    mv_acc2(acc, z2 + r32,  1.f, sW[5]);

    float vals[F];
#pragma unroll
    for (int j = 0; j < 16; j++) unpack2(acc[j], vals[2 * j], vals[2 * j + 1]);
#pragma unroll
    for (int j = F / 2; j < F; j++) vals[j] = fmaxf(vals[j], 0.f);

    float4* op = (float4*)(out + r32);
#pragma unroll
    for (int j = 0; j < 8; j++)
        op[j] = make_float4(vals[4 * j], vals[4 * j + 1], vals[4 * j + 2], vals[4 * j + 3]);
}

// ---------------- BN stats ----------------
__global__ void stats_kernel(const float* __restrict__ v, long long nRows, float* __restrict__ st) {
    int col = threadIdx.x & 31;
    int w = threadIdx.x >> 5;
    int warpsPerBlock = blockDim.x >> 5;
    float s = 0.f, s2 = 0.f;
    for (long long r = (long long)blockIdx.x * warpsPerBlock + w; r < nRows;
         r += (long long)gridDim.x * warpsPerBlock) {
        float val = v[r * F + col];
        s += val;
        s2 += val * val;
    }
    __shared__ float sm[2][8][F];
    sm[0][w][col] = s;
    sm[1][w][col] = s2;
    __syncthreads();
    if (threadIdx.x < F) {
        float a = 0.f, b = 0.f;
#pragma unroll
        for (int ww = 0; ww < 8; ww++) { a += sm[0][ww][threadIdx.x]; b += sm[1][ww][threadIdx.x]; }
        atomicAdd(&st[threadIdx.x], a);
        atomicAdd(&st[F + threadIdx.x], b);
    }
}

// ---------------- BN normalize ----------------
__global__ void normalize_kernel(float* __restrict__ v, long long nRows,
                                 const float* __restrict__ st,
                                 const float* __restrict__ scale, const float* __restrict__ bias) {
    __shared__ float mulc[F], addc[F];
    if (threadIdx.x < F) {
        float m = st[threadIdx.x] / (float)nRows;
        float var = st[F + threadIdx.x] / (float)nRows - m * m;
        float inv = rsqrtf(var + 1e-5f);
        float g = inv * scale[threadIdx.x];
        mulc[threadIdx.x] = g;
        addc[threadIdx.x] = bias[threadIdx.x] - m * g;
    }
    __syncthreads();
    int col = threadIdx.x & 31;
    int w = threadIdx.x >> 5;
    int warpsPerBlock = blockDim.x >> 5;
    for (long long r = (long long)blockIdx.x * warpsPerBlock + w; r < nRows;
         r += (long long)gridDim.x * warpsPerBlock) {
        v[r * F + col] = fmaf(v[r * F + col], mulc[col], addc[col]);
    }
}

// ---------------- launcher ----------------
extern "C" void kernel_launch(void* const* d_in, const int* in_sizes, int n_in,
                              void* d_out, int out_size) {
    const float* x            = (const float*)d_in[0];
    const float* y            = (const float*)d_in[1];
    const float* deg_g        = (const float*)d_in[2];
    const float* deg_lg       = (const float*)d_in[3];
    const float* theta_main_w = (const float*)d_in[4];
    const float* theta_main_b = (const float*)d_in[5];
    const float* theta_list_w = (const float*)d_in[6];
    const float* theta_list_b = (const float*)d_in[7];
    const float* gamma_main_w = (const float*)d_in[8];
    const float* gamma_main_b = (const float*)d_in[9];
    const float* gamma_list_w = (const float*)d_in[10];
    const float* gamma_list_b = (const float*)d_in[11];
    const float* bn_x_scale   = (const float*)d_in[12];
    const float* bn_x_bias    = (const float*)d_in[13];
    const float* bn_y_scale   = (const float*)d_in[14];
    const float* bn_y_bias    = (const float*)d_in[15];
    const int*   g_src        = (const int*)d_in[16];
    const int*   g_dst        = (const int*)d_in[17];
    const int*   lg_src       = (const int*)d_in[18];
    const int*   lg_dst       = (const int*)d_in[19];
    const int*   pm_pd        = (const int*)d_in[20];

    float* out_x = (float*)d_out;
    float* out_y = (float*)d_out + (size_t)NN * F;

    float *zg0, *zg1, *zg2, *zgt, *pmy, *zl0, *zl1, *zl2, *zlt, *st;
    int *cnt_g, *off_g, *cur_g, *csr_src_g, *csr_eid_g;
    int *cnt_lg, *off_lg, *cur_lg, *csr_lg, *bsum;
    cudaGetSymbolAddress((void**)&zg0, d_zg0);
    cudaGetSymbolAddress((void**)&zg1, d_zg1);
    cudaGetSymbolAddress((void**)&zg2, d_zg2);
    cudaGetSymbolAddress((void**)&zgt, d_zgt);
    cudaGetSymbolAddress((void**)&pmy, d_pmy);
    cudaGetSymbolAddress((void**)&zl0, d_zl0);
    cudaGetSymbolAddress((void**)&zl1, d_zl1);
    cudaGetSymbolAddress((void**)&zl2, d_zl2);
    cudaGetSymbolAddress((void**)&zlt, d_zlt);
    cudaGetSymbolAddress((void**)&st,  d_stats);
    cudaGetSymbolAddress((void**)&cnt_g, d_cnt_g);
    cudaGetSymbolAddress((void**)&off_g, d_off_g);
    cudaGetSymbolAddress((void**)&cur_g, d_cur_g);
    cudaGetSymbolAddress((void**)&csr_src_g, d_csr_src_g);
    cudaGetSymbolAddress((void**)&csr_eid_g, d_csr_eid_g);
    cudaGetSymbolAddress((void**)&cnt_lg, d_cnt_lg);
    cudaGetSymbolAddress((void**)&off_lg, d_off_lg);
    cudaGetSymbolAddress((void**)&cur_lg, d_cur_lg);
    cudaGetSymbolAddress((void**)&csr_lg, d_csr_lg);
    cudaGetSymbolAddress((void**)&bsum, d_bsum);

    const int TB = 256;
    int eBlocksG  = (NE + TB - 1) / TB;
    int eBlocksLG = (NLE + TB - 1) / TB;
    int sBlocksG  = (NN + SCAN_B - 1) / SCAN_B;   // 49
    int sBlocksLG = (NE + SCAN_B - 1) / SCAN_B;   // 391

    // ===== build CSR for g (by g_dst), storing both src node and edge id =====
    cudaMemsetAsync(cnt_g, 0, NN * sizeof(int));
    hist_kernel<<<eBlocksG, TB>>>(g_dst, NE, cnt_g);
    scan_block_kernel<<<sBlocksG, SCAN_B>>>(cnt_g, NN, cur_g, bsum);
    scan_bsums_kernel<<<1, SCAN_B>>>(bsum, sBlocksG);
    scan_add_kernel<<<sBlocksG, SCAN_B>>>(cur_g, NN, bsum, off_g);
    cudaMemcpyAsync(cur_g, off_g, NN * sizeof(int), cudaMemcpyDeviceToDevice);
    fill_g_kernel<<<eBlocksG, TB>>>(g_src, g_dst, NE, cur_g, csr_src_g, csr_eid_g);

    // ===== build CSR for lg (by lg_dst) =====
    cudaMemsetAsync(cnt_lg, 0, NE * sizeof(int));
    hist_kernel<<<eBlocksLG, TB>>>(lg_dst, NLE, cnt_lg);
    scan_block_kernel<<<sBlocksLG, SCAN_B>>>(cnt_lg, NE, cur_lg, bsum);
    scan_bsums_kernel<<<1, SCAN_B>>>(bsum, sBlocksLG);
    scan_add_kernel<<<sBlocksLG, SCAN_B>>>(cur_lg, NE, bsum, off_lg);
    cudaMemcpyAsync(cur_lg, off_lg, NE * sizeof(int), cudaMemcpyDeviceToDevice);
    fill_lg_kernel<<<eBlocksLG, TB>>>(lg_src, lg_dst, NLE, cur_lg, csr_lg);

    int pBlocksG  = (NN * 8 + TB - 1) / TB;
    int pBlocksLG = (NE * 8 + TB - 1) / TB;

    // ===== x branch: hops 1, 2, 4 over g =====
    spmm_pull_kernel<<<pBlocksG, TB>>>(x,   off_g, csr_src_g, zg0, NN);
    spmm_pull_kernel<<<pBlocksG, TB>>>(zg0, off_g, csr_src_g, zg1, NN);
    spmm_pull_kernel<<<pBlocksG, TB>>>(zg1, off_g, csr_src_g, zgt, NN);
    spmm_pull_kernel<<<pBlocksG, TB>>>(zgt, off_g, csr_src_g, zg2, NN);
    // pmpd_y = segment_sum(y, g_dst): pull y rows by edge id
    spmm_pull_kernel<<<pBlocksG, TB>>>(y,   off_g, csr_eid_g, pmy, NN);

    assemble_kernel<<<(NN + TB - 1) / TB, TB>>>(
        x, deg_g, pmy, nullptr, zg0, zg1, zg2,
        theta_main_w, theta_main_b, theta_list_w, theta_list_b, out_x, NN);

    // ===== y branch: hops 1, 2, 4 over lg =====
    spmm_pull_kernel<<<pBlocksLG, TB>>>(y,   off_lg, csr_lg, zl0, NE);
    spmm_pull_kernel<<<pBlocksLG, TB>>>(zl0, off_lg, csr_lg, zl1, NE);
    spmm_pull_kernel<<<pBlocksLG, TB>>>(zl1, off_lg, csr_lg, zlt, NE);
    spmm_pull_kernel<<<pBlocksLG, TB>>>(zlt, off_lg, csr_lg, zl2, NE);

    assemble_kernel<<<(NE + TB - 1) / TB, TB>>>(
        y, deg_lg, x, pm_pd, zl0, zl1, zl2,
        gamma_main_w, gamma_main_b, gamma_list_w, gamma_list_b, out_y, NE);

    // ===== batchnorm =====
    cudaMemsetAsync(st, 0, 128 * sizeof(float));
    stats_kernel<<<2048, TB>>>(out_x, NN, st);
    stats_kernel<<<2048, TB>>>(out_y, NE, st + 64);
    normalize_kernel<<<2048, TB>>>(out_x, NN, st, bn_x_scale, bn_x_bias);
    normalize_kernel<<<2048, TB>>>(out_y, NE, st + 64, bn_y_scale, bn_y_bias);
}

// round 3
// speedup vs baseline: 1.4646x; 1.0938x over previous
#include <cuda_runtime.h>
#include <cstddef>

#define NN   50000      // nodes of g
#define NE   400000     // edges of g == nodes of lg
#define NLE  3200000    // edges of lg
#define F    32
#define SCAN_B 1024
#define SBG   ((NN + SCAN_B - 1) / SCAN_B)   // 49
#define SBL   ((NE + SCAN_B - 1) / SCAN_B)   // 391

typedef unsigned long long u64;

// ---------------- scratch (device globals) ----------------
__device__ float d_zg0[NN * F];
__device__ float d_zg1[NN * F];
__device__ float d_zg2[NN * F];
__device__ float d_zgt[NN * F];
__device__ float d_pmy[NN * F];
__device__ float d_zl0[NE * F];
__device__ float d_zl1[NE * F];
__device__ float d_zl2[NE * F];
__device__ float d_zlt[NE * F];
__device__ float d_stats[128];

__device__ int d_cnt[NN + NE];          // g at [0,NN), lg at [NN,NN+NE)
__device__ int d_incl[NN + NE];
__device__ int d_cur[NN + NE];
__device__ int d_off[(NN + 1) + (NE + 1)];
__device__ int d_csr_src_g[NE];
__device__ int d_csr_eid_g[NE];
__device__ int d_csr_lg[NLE];
__device__ int d_bsum[1024];            // g bsums at [0,512), lg at [512,1024)

// ---------------- f32x2 helpers ----------------
__device__ __forceinline__ u64 pack2(float a, float b) {
    u64 r; asm("mov.b64 %0, {%1, %2};" : "=l"(r) : "f"(a), "f"(b)); return r;
}
__device__ __forceinline__ void unpack2(u64 v, float& a, float& b) {
    asm("mov.b64 {%0, %1}, %2;" : "=f"(a), "=f"(b) : "l"(v));
}
__device__ __forceinline__ u64 fma2(u64 a, u64 b, u64 c) {
    u64 d; asm("fma.rn.f32x2 %0, %1, %2, %3;" : "=l"(d) : "l"(a), "l"(b), "l"(c)); return d;
}

// ================= CSR build (both graphs in one pass) =================
__global__ void hist_both_kernel(const int* __restrict__ g_dst, const int* __restrict__ lg_dst,
                                 int* __restrict__ cnt) {
    int t = blockIdx.x * blockDim.x + threadIdx.x;
    if (t < NE) {
        atomicAdd(&cnt[__ldg(g_dst + t)], 1);
    } else if (t < NE + NLE) {
        atomicAdd(&cnt[NN + __ldg(lg_dst + (t - NE))], 1);
    }
}

__global__ void scan_block_kernel(const int* __restrict__ cnt, int* __restrict__ incl,
                                  int* __restrict__ bsum) {
    __shared__ int sm[SCAN_B];
    int b = blockIdx.x;
    const int* c; int* in; int n; int* bs; int rel;
    if (b < SBG) { c = cnt;        in = incl;        n = NN; bs = bsum;       rel = b; }
    else         { c = cnt + NN;   in = incl + NN;   n = NE; bs = bsum + 512; rel = b - SBG; }
    int i = rel * SCAN_B + threadIdx.x;
    int v = (i < n) ? c[i] : 0;
    sm[threadIdx.x] = v;
    __syncthreads();
    for (int o = 1; o < SCAN_B; o <<= 1) {
        int t = (threadIdx.x >= o) ? sm[threadIdx.x - o] : 0;
        __syncthreads();
        sm[threadIdx.x] += t;
        __syncthreads();
    }
    if (i < n) in[i] = sm[threadIdx.x];
    if (threadIdx.x == SCAN_B - 1) bs[rel] = sm[threadIdx.x];
}

// two independent exclusive scans over bsum[0:512) and bsum[512:1024)
__global__ void scan_bsums_kernel(int* __restrict__ bsum) {
    __shared__ int sm[1024];
    int rel = threadIdx.x & 511;
    int seg = threadIdx.x >> 9;
    int nb = seg ? SBL : SBG;
    int v = (rel < nb) ? bsum[threadIdx.x] : 0;
    sm[threadIdx.x] = v;
    __syncthreads();
    for (int o = 1; o < 512; o <<= 1) {
        int t = (rel >= o) ? sm[threadIdx.x - o] : 0;
        __syncthreads();
        sm[threadIdx.x] += t;
        __syncthreads();
    }
    if (rel < nb) bsum[threadIdx.x] = sm[threadIdx.x] - v;  // exclusive
}

// writes off[i+1] and cur[i] (= exclusive prefix) in one pass
__global__ void scan_add_cur_kernel(const int* __restrict__ incl, const int* __restrict__ cnt,
                                    const int* __restrict__ bsum,
                                    int* __restrict__ off, int* __restrict__ cur) {
    int b = blockIdx.x;
    const int* in; const int* c; int n; const int* bs; int rel; int* o; int* cu;
    if (b < SBG) { in = incl;      c = cnt;      n = NN; bs = bsum;       rel = b;       o = off;          cu = cur; }
    else         { in = incl + NN; c = cnt + NN; n = NE; bs = bsum + 512; rel = b - SBG; o = off + NN + 1; cu = cur + NN; }
    int i = rel * SCAN_B + threadIdx.x;
    if (i < n) {
        int inc = in[i] + bs[rel];
        o[i + 1] = inc;
        cu[i] = inc - c[i];
        if (i == 0) o[0] = 0;
    }
}

__global__ void fill_both_kernel(const int* __restrict__ g_src, const int* __restrict__ g_dst,
                                 const int* __restrict__ lg_src, const int* __restrict__ lg_dst,
                                 int* __restrict__ cur,
                                 int* __restrict__ csr_src_g, int* __restrict__ csr_eid_g,
                                 int* __restrict__ csr_lg) {
    int t = blockIdx.x * blockDim.x + threadIdx.x;
    if (t < NE) {
        int p = atomicAdd(&cur[__ldg(g_dst + t)], 1);
        csr_src_g[p] = __ldg(g_src + t);
        csr_eid_g[p] = t;
    } else if (t < NE + NLE) {
        int e = t - NE;
        int p = atomicAdd(&cur[NN + __ldg(lg_dst + e)], 1);
        csr_lg[p] = __ldg(lg_src + e);
    }
}

// ================= pull SpMM, up to 3 segments per launch =================
__device__ __forceinline__ void pull_row(const float* __restrict__ z, const int* __restrict__ off,
                                         const int* __restrict__ idx, float* __restrict__ out,
                                         int r, int lane) {
    int b = __ldg(off + r), e = __ldg(off + r + 1);
    float4 acc = make_float4(0.f, 0.f, 0.f, 0.f);
    int i = b;
    for (; i + 3 < e; i += 4) {
        int s0 = __ldg(idx + i), s1 = __ldg(idx + i + 1);
        int s2 = __ldg(idx + i + 2), s3 = __ldg(idx + i + 3);
        float4 v0 = *((const float4*)(z + (size_t)s0 * F) + lane);
        float4 v1 = *((const float4*)(z + (size_t)s1 * F) + lane);
        float4 v2 = *((const float4*)(z + (size_t)s2 * F) + lane);
        float4 v3 = *((const float4*)(z + (size_t)s3 * F) + lane);
        acc.x += (v0.x + v1.x) + (v2.x + v3.x);
        acc.y += (v0.y + v1.y) + (v2.y + v3.y);
        acc.z += (v0.z + v1.z) + (v2.z + v3.z);
        acc.w += (v0.w + v1.w) + (v2.w + v3.w);
    }
    for (; i < e; i++) {
        int s0 = __ldg(idx + i);
        float4 v0 = *((const float4*)(z + (size_t)s0 * F) + lane);
        acc.x += v0.x; acc.y += v0.y; acc.z += v0.z; acc.w += v0.w;
    }
    *((float4*)(out + (size_t)r * F) + lane) = acc;
}

__global__ void hops_kernel(
    const float* __restrict__ z1, const int* __restrict__ off1, const int* __restrict__ idx1,
    float* __restrict__ o1, int n1,
    const float* __restrict__ z2, const int* __restrict__ off2, const int* __restrict__ idx2,
    float* __restrict__ o2, int n2,
    const float* __restrict__ z3, const int* __restrict__ off3, const int* __restrict__ idx3,
    float* __restrict__ o3, int n3)
{
    long long t = (long long)blockIdx.x * blockDim.x + threadIdx.x;
    int r = (int)(t >> 3);
    int lane = (int)(t & 7);
    if (r < n1) {
        pull_row(z1, off1, idx1, o1, r, lane);
    } else if (r < n1 + n2) {
        pull_row(z2, off2, idx2, o2, r - n1, lane);
    } else if (r < n1 + n2 + n3) {
        pull_row(z3, off3, idx3, o3, r - n1 - n2, lane);
    }
}

// ================= fused assemble (both branches, f32x2) =================
__device__ __forceinline__ void mv_acc2(u64 acc[16], const float* __restrict__ vec,
                                        float scale, const u64 (&W)[F][16]) {
    const float4* vp = (const float4*)vec;
#pragma unroll 1
    for (int k4 = 0; k4 < 8; k4++) {
        float4 v = vp[k4];
        float c0 = v.x * scale, c1 = v.y * scale, c2 = v.z * scale, c3 = v.w * scale;
        u64 a0 = pack2(c0, c0), a1 = pack2(c1, c1), a2 = pack2(c2, c2), a3 = pack2(c3, c3);
#pragma unroll
        for (int j = 0; j < 16; j++) acc[j] = fma2(a0, W[k4 * 4 + 0][j], acc[j]);
#pragma unroll
        for (int j = 0; j < 16; j++) acc[j] = fma2(a1, W[k4 * 4 + 1][j], acc[j]);
#pragma unroll
        for (int j = 0; j < 16; j++) acc[j] = fma2(a2, W[k4 * 4 + 2][j], acc[j]);
#pragma unroll
        for (int j = 0; j < 16; j++) acc[j] = fma2(a3, W[k4 * 4 + 3][j], acc[j]);
    }
}

__global__ void assemble_both_kernel(
    // x branch
    const float* __restrict__ xb, const float* __restrict__ xdeg, const float* __restrict__ xextra,
    const float* __restrict__ xz0, const float* __restrict__ xz1, const float* __restrict__ xz2,
    const float* __restrict__ xWm, const float* __restrict__ xbm,
    const float* __restrict__ xWl, const float* __restrict__ xbl,
    float* __restrict__ xout, int nx, int bx,
    // y branch
    const float* __restrict__ yb, const float* __restrict__ ydeg, const float* __restrict__ yextra,
    const int* __restrict__ gatherIdx,
    const float* __restrict__ yz0, const float* __restrict__ yz1, const float* __restrict__ yz2,
    const float* __restrict__ yWm, const float* __restrict__ ybm,
    const float* __restrict__ yWl, const float* __restrict__ ybl,
    float* __restrict__ yout, int ny)
{
    bool isX = (int)blockIdx.x < bx;
    const float* base  = isX ? xb : yb;
    const float* deg   = isX ? xdeg : ydeg;
    const float* extra = isX ? xextra : yextra;
    const float* z0 = isX ? xz0 : yz0;
    const float* z1 = isX ? xz1 : yz1;
    const float* z2 = isX ? xz2 : yz2;
    const float* Wmain = isX ? xWm : yWm;
    const float* bmain = isX ? xbm : ybm;
    const float* Wlist = isX ? xWl : yWl;
    const float* blist = isX ? xbl : ybl;
    float* out = isX ? xout : yout;
    int n = isX ? nx : ny;
    int rblock = isX ? (int)blockIdx.x : (int)blockIdx.x - bx;

    __shared__ u64 sW[6][F][16];
    __shared__ u64 sb[16];
    for (int i = threadIdx.x; i < 6 * F * 16; i += blockDim.x) {
        int m = i >> 9;
        int rem = i & 511;
        int k = rem >> 4;
        int j2 = rem & 15;
        const float* W = (m < 3) ? (Wmain + m * 1024) : (Wlist + (m - 3) * 1024);
        sW[m][k][j2] = pack2(W[(2 * j2) * 32 + k], W[(2 * j2 + 1) * 32 + k]);
    }
    if (threadIdx.x < 16) {
        int j2 = threadIdx.x;
        float b0 = 0.f, b1 = 0.f;
#pragma unroll
        for (int m = 0; m < 3; m++) {
            b0 += bmain[m * 32 + 2 * j2] + blist[m * 32 + 2 * j2];
            b1 += bmain[m * 32 + 2 * j2 + 1] + blist[m * 32 + 2 * j2 + 1];
        }
        sb[j2] = pack2(b0, b1);
    }
    __syncthreads();

    int r = rblock * blockDim.x + threadIdx.x;
    if (r >= n) return;

    u64 acc[16];
#pragma unroll
    for (int j = 0; j < 16; j++) acc[j] = sb[j];

    size_t r32 = (size_t)r * F;
    float dg = deg[r];
    mv_acc2(acc, base + r32, 1.f, sW[0]);
    mv_acc2(acc, base + r32, dg,  sW[1]);
    const float* ex = isX ? (extra + r32) : (extra + (size_t)__ldg(gatherIdx + r) * F);
    mv_acc2(acc, ex,        1.f, sW[2]);
    mv_acc2(acc, z0 + r32,  1.f, sW[3]);
    mv_acc2(acc, z1 + r32,  1.f, sW[4]);
    mv_acc2(acc, z2 + r32,  1.f, sW[5]);

    float vals[F];
#pragma unroll
    for (int j = 0; j < 16; j++) unpack2(acc[j], vals[2 * j], vals[2 * j + 1]);
#pragma unroll
    for (int j = F / 2; j < F; j++) vals[j] = fmaxf(vals[j], 0.f);

    float4* op = (float4*)(out + r32);
#pragma unroll
    for (int j = 0; j < 8; j++)
        op[j] = make_float4(vals[4 * j], vals[4 * j + 1], vals[4 * j + 2], vals[4 * j + 3]);
}

// ================= BN stats (both outputs, one launch) =================
__global__ void stats_both_kernel(const float* __restrict__ vx, const float* __restrict__ vy,
                                  int gx, float* __restrict__ st) {
    bool isX = (int)blockIdx.x < gx;
    const float* v = isX ? vx : vy;
    long long nRows = isX ? NN : NE;
    float* s0 = st + (isX ? 0 : 64);
    int nb = isX ? gx : (gridDim.x - gx);
    int rb = isX ? (int)blockIdx.x : (int)blockIdx.x - gx;

    int col = threadIdx.x & 31;
    int w = threadIdx.x >> 5;
    int warpsPerBlock = blockDim.x >> 5;
    float s = 0.f, s2 = 0.f;
    for (long long r = (long long)rb * warpsPerBlock + w; r < nRows;
         r += (long long)nb * warpsPerBlock) {
        float val = v[r * F + col];
        s += val;
        s2 += val * val;
    }
    __shared__ float sm[2][8][F];
    sm[0][w][col] = s;
    sm[1][w][col] = s2;
    __syncthreads();
    if (threadIdx.x < F) {
        float a = 0.f, b = 0.f;
#pragma unroll
        for (int ww = 0; ww < 8; ww++) { a += sm[0][ww][threadIdx.x]; b += sm[1][ww][threadIdx.x]; }
        atomicAdd(&s0[threadIdx.x], a);
        atomicAdd(&s0[F + threadIdx.x], b);
    }
}

// ================= BN normalize (both outputs) =================
__global__ void normalize_both_kernel(float* __restrict__ vx, float* __restrict__ vy,
                                      int gx, const float* __restrict__ st,
                                      const float* __restrict__ sx, const float* __restrict__ bxx,
                                      const float* __restrict__ sy, const float* __restrict__ byy) {
    bool isX = (int)blockIdx.x < gx;
    float* v = isX ? vx : vy;
    long long nRows = isX ? NN : NE;
    const float* s0 = st + (isX ? 0 : 64);
    const float* scale = isX ? sx : sy;
    const float* bias  = isX ? bxx : byy;
    int nb = isX ? gx : (gridDim.x - gx);
    int rb = isX ? (int)blockIdx.x : (int)blockIdx.x - gx;

    __shared__ float mulc[F], addc[F];
    if (threadIdx.x < F) {
        float m = s0[threadIdx.x] / (float)nRows;
        float var = s0[F + threadIdx.x] / (float)nRows - m * m;
        float g = rsqrtf(var + 1e-5f) * scale[threadIdx.x];
        mulc[threadIdx.x] = g;
        addc[threadIdx.x] = bias[threadIdx.x] - m * g;
    }
    __syncthreads();
    int col = threadIdx.x & 31;
    int w = threadIdx.x >> 5;
    int warpsPerBlock = blockDim.x >> 5;
    for (long long r = (long long)rb * warpsPerBlock + w; r < nRows;
         r += (long long)nb * warpsPerBlock) {
        v[r * F + col] = fmaf(v[r * F + col], mulc[col], addc[col]);
    }
}

// ================= launcher =================
extern "C" void kernel_launch(void* const* d_in, const int* in_sizes, int n_in,
                              void* d_out, int out_size) {
    const float* x            = (const float*)d_in[0];
    const float* y            = (const float*)d_in[1];
    const float* deg_g        = (const float*)d_in[2];
    const float* deg_lg       = (const float*)d_in[3];
    const float* theta_main_w = (const float*)d_in[4];
    const float* theta_main_b = (const float*)d_in[5];
    const float* theta_list_w = (const float*)d_in[6];
    const float* theta_list_b = (const float*)d_in[7];
    const float* gamma_main_w = (const float*)d_in[8];
    const float* gamma_main_b = (const float*)d_in[9];
    const float* gamma_list_w = (const float*)d_in[10];
    const float* gamma_list_b = (const float*)d_in[11];
    const float* bn_x_scale   = (const float*)d_in[12];
    const float* bn_x_bias    = (const float*)d_in[13];
    const float* bn_y_scale   = (const float*)d_in[14];
    const float* bn_y_bias    = (const float*)d_in[15];
    const int*   g_src        = (const int*)d_in[16];
    const int*   g_dst        = (const int*)d_in[17];
    const int*   lg_src       = (const int*)d_in[18];
    const int*   lg_dst       = (const int*)d_in[19];
    const int*   pm_pd        = (const int*)d_in[20];

    float* out_x = (float*)d_out;
    float* out_y = (float*)d_out + (size_t)NN * F;

    float *zg0, *zg1, *zg2, *zgt, *pmy, *zl0, *zl1, *zl2, *zlt, *st;
    int *cnt, *incl, *cur, *off, *csr_src_g, *csr_eid_g, *csr_lg, *bsum;
    cudaGetSymbolAddress((void**)&zg0, d_zg0);
    cudaGetSymbolAddress((void**)&zg1, d_zg1);
    cudaGetSymbolAddress((void**)&zg2, d_zg2);
    cudaGetSymbolAddress((void**)&zgt, d_zgt);
    cudaGetSymbolAddress((void**)&pmy, d_pmy);
    cudaGetSymbolAddress((void**)&zl0, d_zl0);
    cudaGetSymbolAddress((void**)&zl1, d_zl1);
    cudaGetSymbolAddress((void**)&zl2, d_zl2);
    cudaGetSymbolAddress((void**)&zlt, d_zlt);
    cudaGetSymbolAddress((void**)&st,  d_stats);
    cudaGetSymbolAddress((void**)&cnt, d_cnt);
    cudaGetSymbolAddress((void**)&incl, d_incl);
    cudaGetSymbolAddress((void**)&cur, d_cur);
    cudaGetSymbolAddress((void**)&off, d_off);
    cudaGetSymbolAddress((void**)&csr_src_g, d_csr_src_g);
    cudaGetSymbolAddress((void**)&csr_eid_g, d_csr_eid_g);
    cudaGetSymbolAddress((void**)&csr_lg, d_csr_lg);
    cudaGetSymbolAddress((void**)&bsum, d_bsum);

    int* off_g  = off;
    int* off_lg = off + NN + 1;

    const int TB = 256;
    int eBlocks = (NE + NLE + TB - 1) / TB;

    // ===== CSR build (g + lg fused) =====
    cudaMemsetAsync(cnt, 0, (NN + NE) * sizeof(int));
    hist_both_kernel<<<eBlocks, TB>>>(g_dst, lg_dst, cnt);
    scan_block_kernel<<<SBG + SBL, SCAN_B>>>(cnt, incl, bsum);
    scan_bsums_kernel<<<1, SCAN_B>>>(bsum);
    scan_add_cur_kernel<<<SBG + SBL, SCAN_B>>>(incl, cnt, bsum, off, cur);
    fill_both_kernel<<<eBlocks, TB>>>(g_src, g_dst, lg_src, lg_dst, cur,
                                      csr_src_g, csr_eid_g, csr_lg);

    // ===== hops (lg + g fused per hop; hop1 also does pmpd_y) =====
    long long rows1 = (long long)(NE + NN + NN) * 8;
    long long rows  = (long long)(NE + NN) * 8;
    int hBlocks1 = (int)((rows1 + TB - 1) / TB);
    int hBlocks  = (int)((rows + TB - 1) / TB);

    hops_kernel<<<hBlocks1, TB>>>(y,   off_lg, csr_lg, zl0, NE,
                                  x,   off_g, csr_src_g, zg0, NN,
                                  y,   off_g, csr_eid_g, pmy, NN);
    hops_kernel<<<hBlocks, TB>>>(zl0, off_lg, csr_lg, zl1, NE,
                                 zg0, off_g, csr_src_g, zg1, NN,
                                 nullptr, nullptr, nullptr, nullptr, 0);
    hops_kernel<<<hBlocks, TB>>>(zl1, off_lg, csr_lg, zlt, NE,
                                 zg1, off_g, csr_src_g, zgt, NN,
                                 nullptr, nullptr, nullptr, nullptr, 0);
    hops_kernel<<<hBlocks, TB>>>(zlt, off_lg, csr_lg, zl2, NE,
                                 zgt, off_g, csr_src_g, zg2, NN,
                                 nullptr, nullptr, nullptr, nullptr, 0);

    // ===== assemble (both branches) =====
    int bx = (NN + TB - 1) / TB;
    int by = (NE + TB - 1) / TB;
    assemble_both_kernel<<<bx + by, TB>>>(
        x, deg_g, pmy, zg0, zg1, zg2,
        theta_main_w, theta_main_b, theta_list_w, theta_list_b, out_x, NN, bx,
        y, deg_lg, x, pm_pd, zl0, zl1, zl2,
        gamma_main_w, gamma_main_b, gamma_list_w, gamma_list_b, out_y, NE);

    // ===== batchnorm =====
    cudaMemsetAsync(st, 0, 128 * sizeof(float));
    stats_both_kernel<<<512 + 2048, TB>>>(out_x, out_y, 512, st);
    normalize_both_kernel<<<512 + 2048, TB>>>(out_x, out_y, 512, st,
                                              bn_x_scale, bn_x_bias, bn_y_scale, bn_y_bias);
}